// round 4
// baseline (speedup 1.0000x reference)
#include <cuda_runtime.h>
#include <math.h>

#define B_  1024
#define N_  1024
#define M_  128
#define C_  1024
#define OUTF 390
#define EPS 1e-16f
#define KSPLIT 4
#define KCHUNK (C_ / KSPLIT)   // 256
#define BCHUNK 128             // batches per L2-resident chunk (67 MB of memory)

// ---------------- scratch ----------------
__device__ float g_part[KSPLIT * B_ * OUTF];  // split-K partials
__device__ float g_o[B_ * OUTF];              // GEMM output (k|beta|g|s0..2|gamma|e|a)
__device__ float g_logits[B_ * N_];           // beta * cosine sim
__device__ float g_scal[B_ * 8];              // beta,g,gamma,knorm,s0,s1,s2

// ---------------- K1: split-K SGEMM 1024 x 390 x 1024 ----------------
__global__ void k1_gemm(const float* __restrict__ A,
                        const float* __restrict__ Bm)
{
    __shared__ float As[16][65];
    __shared__ float Bs[16][68];

    const int tid = threadIdx.x;
    const int tx  = tid & 15;
    const int ty  = tid >> 4;
    const int row0 = blockIdx.y * 64;
    const int col0 = blockIdx.x * 64;
    const int ks   = blockIdx.z;
    const int kbeg = ks * KCHUNK;

    float acc[4][4];
#pragma unroll
    for (int i = 0; i < 4; i++)
#pragma unroll
        for (int j = 0; j < 4; j++) acc[i][j] = 0.f;

    const int ar  = tid >> 2;
    const int ac4 = (tid & 3) * 4;
    const int bkr = tid >> 4;
    const int bcc = (tid & 15) * 4;

    for (int k0 = kbeg; k0 < kbeg + KCHUNK; k0 += 16) {
        float4 av = *(const float4*)&A[(size_t)(row0 + ar) * C_ + k0 + ac4];
        As[ac4 + 0][ar] = av.x;
        As[ac4 + 1][ar] = av.y;
        As[ac4 + 2][ar] = av.z;
        As[ac4 + 3][ar] = av.w;
#pragma unroll
        for (int j = 0; j < 4; j++) {
            int col = col0 + bcc + j;
            Bs[bkr][bcc + j] = (col < OUTF) ? Bm[(size_t)(k0 + bkr) * OUTF + col] : 0.f;
        }
        __syncthreads();

#pragma unroll
        for (int kk = 0; kk < 16; kk++) {
            float ra[4], rb[4];
#pragma unroll
            for (int i = 0; i < 4; i++) ra[i] = As[kk][ty * 4 + i];
            float4 rb4 = *(const float4*)&Bs[kk][tx * 4];
            rb[0] = rb4.x; rb[1] = rb4.y; rb[2] = rb4.z; rb[3] = rb4.w;
#pragma unroll
            for (int i = 0; i < 4; i++)
#pragma unroll
                for (int j = 0; j < 4; j++) acc[i][j] = fmaf(ra[i], rb[j], acc[i][j]);
        }
        __syncthreads();
    }

    float* part = &g_part[(size_t)ks * B_ * OUTF];
#pragma unroll
    for (int i = 0; i < 4; i++) {
        int row = row0 + ty * 4 + i;
#pragma unroll
        for (int j = 0; j < 4; j++) {
            int col = col0 + tx * 4 + j;
            if (col < OUTF)
                part[(size_t)row * OUTF + col] = acc[i][j];
        }
    }
}

// ---------------- K1b: reduce partials + bias ----------------
__global__ void k1b_reduce(const float* __restrict__ bias)
{
    const int idx = blockIdx.x * 256 + threadIdx.x;
    if (idx >= B_ * OUTF) return;
    const int col = idx % OUTF;
    float s = g_part[idx]
            + g_part[(size_t)1 * B_ * OUTF + idx]
            + g_part[(size_t)2 * B_ * OUTF + idx]
            + g_part[(size_t)3 * B_ * OUTF + idx];
    g_o[idx] = s + bias[col];
}

// ---------------- K2: per-batch activations + k-norm ----------------
__device__ __forceinline__ float softplus_f(float x) {
    return (x > 0.f) ? (x + log1pf(expf(-x))) : log1pf(expf(x));
}
__device__ __forceinline__ float sigmoid_f(float x) {
    return 1.f / (1.f + expf(-x));
}

__global__ void k2_act()   // grid = B_, block = 128
{
    const int b   = blockIdx.x;
    const int tid = threadIdx.x;
    float* o = &g_o[(size_t)b * OUTF];

    float kv = o[tid];
    float ss = kv * kv;
#pragma unroll
    for (int off = 16; off > 0; off >>= 1)
        ss += __shfl_xor_sync(0xffffffffu, ss, off);
    __shared__ float red[4];
    if ((tid & 31) == 0) red[tid >> 5] = ss;
    __syncthreads();

    if (tid == 0) {
        float ksq = red[0] + red[1] + red[2] + red[3];
        float knorm = sqrtf(ksq);
        float beta  = softplus_f(o[M_]);
        float g     = sigmoid_f(o[M_ + 1]);
        float s0 = o[M_ + 2], s1 = o[M_ + 3], s2 = o[M_ + 4];
        float mx = fmaxf(s0, fmaxf(s1, s2));
        float e0 = expf(s0 - mx), e1 = expf(s1 - mx), e2 = expf(s2 - mx);
        float es = e0 + e1 + e2;
        float gamma = 1.f + softplus_f(o[M_ + 5]);
        float* sc = &g_scal[b * 8];
        sc[0] = beta; sc[1] = g; sc[2] = gamma; sc[3] = knorm;
        sc[4] = e0 / es; sc[5] = e1 / es; sc[6] = e2 / es;
    }
    o[M_ + 6 + tid] = sigmoid_f(o[M_ + 6 + tid]);
}

// ---------------- K3: logits = beta * cosine(memory_row, k) ----------------
// grid: (N_/32, BCHUNK), block 256 (8 warps), each warp handles 4 rows
__global__ void k3_sim(const float* __restrict__ mem, int b0)
{
    const int b    = b0 + blockIdx.y;
    const int tid  = threadIdx.x;
    const int warp = tid >> 5;
    const int lane = tid & 31;

    __shared__ float sk[M_];
    if (tid < M_) sk[tid] = g_o[(size_t)b * OUTF + tid];
    __syncthreads();

    const float beta  = g_scal[b * 8 + 0];
    const float knorm = g_scal[b * 8 + 3];
    const float4 k4   = *(const float4*)&sk[lane * 4];

    const int nbase = blockIdx.x * 32 + warp * 4;
    float dot[4], ssq[4];
#pragma unroll
    for (int i = 0; i < 4; i++) {
        const float4 mv = *(const float4*)&mem[((size_t)b * N_ + (nbase + i)) * M_ + lane * 4];
        dot[i] = mv.x * k4.x + mv.y * k4.y + mv.z * k4.z + mv.w * k4.w;
        ssq[i] = mv.x * mv.x + mv.y * mv.y + mv.z * mv.z + mv.w * mv.w;
    }
#pragma unroll
    for (int off = 16; off > 0; off >>= 1) {
#pragma unroll
        for (int i = 0; i < 4; i++) {
            dot[i] += __shfl_xor_sync(0xffffffffu, dot[i], off);
            ssq[i] += __shfl_xor_sync(0xffffffffu, ssq[i], off);
        }
    }
    if (lane < 4) {
        int i = lane;
        float sim = dot[i] / (sqrtf(ssq[i]) * knorm + EPS);
        g_logits[(size_t)b * N_ + nbase + i] = beta * sim;
    }
}

// ---------------- K4: softmax -> gate -> shift conv -> sharpen -> w ----------------
__global__ void k4_weight(const float* __restrict__ w_prev, float* __restrict__ w_out, int b0)
{
    const int b   = b0 + blockIdx.x;
    const int tid = threadIdx.x;

    __shared__ float swg[N_];
    __shared__ float sred[8];

    const float* lg = &g_logits[(size_t)b * N_];
    const float* sc = &g_scal[b * 8];
    const float g = sc[1], gamma = sc[2], s0 = sc[4], s1 = sc[5], s2 = sc[6];

    float x[4];
    float lmax = -1e30f;
#pragma unroll
    for (int j = 0; j < 4; j++) {
        x[j] = lg[tid + 256 * j];
        lmax = fmaxf(lmax, x[j]);
    }
#pragma unroll
    for (int off = 16; off > 0; off >>= 1)
        lmax = fmaxf(lmax, __shfl_xor_sync(0xffffffffu, lmax, off));
    if ((tid & 31) == 0) sred[tid >> 5] = lmax;
    __syncthreads();
    float bmax = sred[0];
#pragma unroll
    for (int k = 1; k < 8; k++) bmax = fmaxf(bmax, sred[k]);

    float p[4];
    float lsum = 0.f;
#pragma unroll
    for (int j = 0; j < 4; j++) { p[j] = expf(x[j] - bmax); lsum += p[j]; }
#pragma unroll
    for (int off = 16; off > 0; off >>= 1)
        lsum += __shfl_xor_sync(0xffffffffu, lsum, off);
    __syncthreads();
    if ((tid & 31) == 0) sred[tid >> 5] = lsum;
    __syncthreads();
    float bsum = 0.f;
#pragma unroll
    for (int k = 0; k < 8; k++) bsum += sred[k];
    float inv = 1.f / bsum;

    const float* wp = &w_prev[(size_t)b * N_];
#pragma unroll
    for (int j = 0; j < 4; j++) {
        int i = tid + 256 * j;
        float wc = p[j] * inv;
        swg[i] = g * wc + (1.f - g) * wp[i];
    }
    __syncthreads();

    float wpow[4];
    float lsum2 = 0.f;
#pragma unroll
    for (int j = 0; j < 4; j++) {
        int i = tid + 256 * j;
        float wt = s0 * swg[(i + N_ - 1) & (N_ - 1)] + s1 * swg[i] + s2 * swg[(i + 1) & (N_ - 1)];
        wpow[j] = powf(wt + EPS, gamma);
        lsum2 += wpow[j];
    }
#pragma unroll
    for (int off = 16; off > 0; off >>= 1)
        lsum2 += __shfl_xor_sync(0xffffffffu, lsum2, off);
    __syncthreads();
    if ((tid & 31) == 0) sred[tid >> 5] = lsum2;
    __syncthreads();
    float bsum2 = 0.f;
#pragma unroll
    for (int k = 0; k < 8; k++) bsum2 += sred[k];
    float inv2 = 1.f / (bsum2 + EPS);

#pragma unroll
    for (int j = 0; j < 4; j++)
        w_out[(size_t)b * N_ + tid + 256 * j] = wpow[j] * inv2;
}

// ---------------- K5: new_memory = mem*(1 - w e) + w a ----------------
// mem chunk should be L2-resident from k3; stores evict-first to protect L2
__global__ void k5_update(const float* __restrict__ mem,
                          const float* __restrict__ w,
                          float* __restrict__ out_mem, int b0)
{
    const int b    = b0 + blockIdx.y;
    const int tid  = threadIdx.x;
    const int warp = tid >> 5;
    const int lane = tid & 31;

    __shared__ float se[M_];
    __shared__ float sa[M_];
    if (tid < M_) {
        se[tid] = g_o[(size_t)b * OUTF + M_ + 6 + tid];
        sa[tid] = g_o[(size_t)b * OUTF + 2 * M_ + 6 + tid];
    }
    __syncthreads();

    const float4 ev = *(const float4*)&se[lane * 4];
    const float4 av = *(const float4*)&sa[lane * 4];

    const int nbase = blockIdx.x * 32 + warp * 4;
#pragma unroll
    for (int i = 0; i < 4; i++) {
        const int n = nbase + i;
        const float wv = w[(size_t)b * N_ + n];
        const size_t off = ((size_t)b * N_ + n) * M_ + lane * 4;
        float4 mv = *(const float4*)&mem[off];           // L2 hit (chunk resident)
        float4 r;
        r.x = mv.x * (1.f - wv * ev.x) + wv * av.x;
        r.y = mv.y * (1.f - wv * ev.y) + wv * av.y;
        r.z = mv.z * (1.f - wv * ev.z) + wv * av.z;
        r.w = mv.w * (1.f - wv * ev.w) + wv * av.w;
        __stcs((float4*)&out_mem[off], r);               // evict-first write
    }
}

// ---------------- launch ----------------
extern "C" void kernel_launch(void* const* d_in, const int* in_sizes, int n_in,
                              void* d_out, int out_size)
{
    const float* emb    = (const float*)d_in[0];
    const float* w_prev = (const float*)d_in[1];
    const float* mem    = (const float*)d_in[2];
    const float* fc_w   = (const float*)d_in[3];
    const float* fc_b   = (const float*)d_in[4];

    float* out_w   = (float*)d_out;
    float* out_mem = out_w + (size_t)B_ * N_;

    dim3 g1((OUTF + 63) / 64, B_ / 64, KSPLIT);
    k1_gemm<<<g1, 256>>>(emb, fc_w);
    k1b_reduce<<<(B_ * OUTF + 255) / 256, 256>>>(fc_b);
    k2_act<<<B_, 128>>>();

    dim3 g3(N_ / 32, BCHUNK);
    for (int b0 = 0; b0 < B_; b0 += BCHUNK) {
        k3_sim<<<g3, 256>>>(mem, b0);
        k4_weight<<<BCHUNK, 256>>>(w_prev, out_w, b0);
        k5_update<<<g3, 256>>>(mem, out_w, out_mem, b0);
    }
}

// round 5
// speedup vs baseline: 1.1036x; 1.1036x over previous
#include <cuda_runtime.h>
#include <math.h>

#define B_  1024
#define N_  1024
#define M_  128
#define C_  1024
#define OUTF 390
#define EPS 1e-16f
#define KSPLIT 4
#define KCHUNK (C_ / KSPLIT)   // 256

// ---------------- scratch ----------------
__device__ float g_part[KSPLIT * B_ * OUTF];
__device__ float g_o[B_ * OUTF];     // GEMM output (k|beta|g|s0..2|gamma|e|a)
__device__ float g_scal[B_ * 8];     // beta,g,gamma,knorm,s0,s1,s2

// ---------------- K1: split-K SGEMM 1024 x 390 x 1024 ----------------
__global__ void k1_gemm(const float* __restrict__ A,
                        const float* __restrict__ Bm)
{
    __shared__ float As[16][65];
    __shared__ float Bs[16][68];

    const int tid = threadIdx.x;
    const int tx  = tid & 15;
    const int ty  = tid >> 4;
    const int row0 = blockIdx.y * 64;
    const int col0 = blockIdx.x * 64;
    const int ks   = blockIdx.z;
    const int kbeg = ks * KCHUNK;

    float acc[4][4];
#pragma unroll
    for (int i = 0; i < 4; i++)
#pragma unroll
        for (int j = 0; j < 4; j++) acc[i][j] = 0.f;

    const int ar  = tid >> 2;
    const int ac4 = (tid & 3) * 4;
    const int bkr = tid >> 4;
    const int bcc = (tid & 15) * 4;

    for (int k0 = kbeg; k0 < kbeg + KCHUNK; k0 += 16) {
        float4 av = *(const float4*)&A[(size_t)(row0 + ar) * C_ + k0 + ac4];
        As[ac4 + 0][ar] = av.x;
        As[ac4 + 1][ar] = av.y;
        As[ac4 + 2][ar] = av.z;
        As[ac4 + 3][ar] = av.w;
#pragma unroll
        for (int j = 0; j < 4; j++) {
            int col = col0 + bcc + j;
            Bs[bkr][bcc + j] = (col < OUTF) ? Bm[(size_t)(k0 + bkr) * OUTF + col] : 0.f;
        }
        __syncthreads();

#pragma unroll
        for (int kk = 0; kk < 16; kk++) {
            float ra[4], rb[4];
#pragma unroll
            for (int i = 0; i < 4; i++) ra[i] = As[kk][ty * 4 + i];
            float4 rb4 = *(const float4*)&Bs[kk][tx * 4];
            rb[0] = rb4.x; rb[1] = rb4.y; rb[2] = rb4.z; rb[3] = rb4.w;
#pragma unroll
            for (int i = 0; i < 4; i++)
#pragma unroll
                for (int j = 0; j < 4; j++) acc[i][j] = fmaf(ra[i], rb[j], acc[i][j]);
        }
        __syncthreads();
    }

    float* part = &g_part[(size_t)ks * B_ * OUTF];
#pragma unroll
    for (int i = 0; i < 4; i++) {
        int row = row0 + ty * 4 + i;
#pragma unroll
        for (int j = 0; j < 4; j++) {
            int col = col0 + tx * 4 + j;
            if (col < OUTF)
                part[(size_t)row * OUTF + col] = acc[i][j];
        }
    }
}

// ---------------- K1b: reduce partials + bias ----------------
__global__ void k1b_reduce(const float* __restrict__ bias)
{
    const int idx = blockIdx.x * 256 + threadIdx.x;
    if (idx >= B_ * OUTF) return;
    const int col = idx % OUTF;
    float s = g_part[idx]
            + g_part[(size_t)1 * B_ * OUTF + idx]
            + g_part[(size_t)2 * B_ * OUTF + idx]
            + g_part[(size_t)3 * B_ * OUTF + idx];
    g_o[idx] = s + bias[col];
}

// ---------------- K2: per-batch activations + k-norm ----------------
__device__ __forceinline__ float softplus_f(float x) {
    return (x > 0.f) ? (x + log1pf(expf(-x))) : log1pf(expf(x));
}
__device__ __forceinline__ float sigmoid_f(float x) {
    return 1.f / (1.f + expf(-x));
}

__global__ void k2_act()   // grid = B_, block = 128
{
    const int b   = blockIdx.x;
    const int tid = threadIdx.x;
    float* o = &g_o[(size_t)b * OUTF];

    float kv = o[tid];
    float ss = kv * kv;
#pragma unroll
    for (int off = 16; off > 0; off >>= 1)
        ss += __shfl_xor_sync(0xffffffffu, ss, off);
    __shared__ float red[4];
    if ((tid & 31) == 0) red[tid >> 5] = ss;
    __syncthreads();

    if (tid == 0) {
        float ksq = red[0] + red[1] + red[2] + red[3];
        float knorm = sqrtf(ksq);
        float beta  = softplus_f(o[M_]);
        float g     = sigmoid_f(o[M_ + 1]);
        float s0 = o[M_ + 2], s1 = o[M_ + 3], s2 = o[M_ + 4];
        float mx = fmaxf(s0, fmaxf(s1, s2));
        float e0 = expf(s0 - mx), e1 = expf(s1 - mx), e2 = expf(s2 - mx);
        float es = e0 + e1 + e2;
        float gamma = 1.f + softplus_f(o[M_ + 5]);
        float* sc = &g_scal[b * 8];
        sc[0] = beta; sc[1] = g; sc[2] = gamma; sc[3] = knorm;
        sc[4] = e0 / es; sc[5] = e1 / es; sc[6] = e2 / es;
    }
    o[M_ + 6 + tid] = sigmoid_f(o[M_ + 6 + tid]);
}

// ---------------- KF: fused sim + weighting + update, one CTA per batch ----------------
// 1024 threads (32 warps, 32 rows/warp). Dynamic SMEM padded to force 1 CTA/SM
// so the 148 resident batches' memory slices (76 MB) stay L2-resident between
// pass 1 (read, allocate-normal) and pass 2 (read __ldcs, write __stcs).
__global__ void __launch_bounds__(1024, 1)
kF_fused(const float* __restrict__ mem,
         const float* __restrict__ w_prev,
         float* __restrict__ w_out,
         float* __restrict__ out_mem)
{
    extern __shared__ float sh[];
    float* sk   = sh;            // 128
    float* se   = sk + 128;      // 128
    float* sa   = se + 128;      // 128
    float* slog = sa + 128;      // 1024: logits -> w_g (in place)
    float* warr = slog + 1024;   // 1024: final w
    float* sred = warr + 1024;   // 32

    const int b    = blockIdx.x;
    const int tid  = threadIdx.x;
    const int warp = tid >> 5;
    const int lane = tid & 31;

    if (tid < 128) {
        sk[tid] = g_o[(size_t)b * OUTF + tid];
        se[tid] = g_o[(size_t)b * OUTF + M_ + 6 + tid];
        sa[tid] = g_o[(size_t)b * OUTF + 2 * M_ + 6 + tid];
    }
    __syncthreads();

    const float beta  = g_scal[b * 8 + 0];
    const float g     = g_scal[b * 8 + 1];
    const float gamma = g_scal[b * 8 + 2];
    const float knorm = g_scal[b * 8 + 3];
    const float s0    = g_scal[b * 8 + 4];
    const float s1    = g_scal[b * 8 + 5];
    const float s2    = g_scal[b * 8 + 6];

    const float4 k4 = *(const float4*)&sk[lane * 4];
    const float4 ev = *(const float4*)&se[lane * 4];
    const float4 av = *(const float4*)&sa[lane * 4];

    const float* memb = mem + (size_t)b * N_ * M_;

    // ---- pass 1: logits = beta * cos(mem_row, k) ----
    // 32 warps x 32 rows, 4 rows in flight per warp
#pragma unroll
    for (int i0 = 0; i0 < 32; i0 += 4) {
        const int nbase = warp * 32 + i0;
        float dot[4], ssq[4];
#pragma unroll
        for (int i = 0; i < 4; i++) {
            const float4 mv = *(const float4*)&memb[(size_t)(nbase + i) * M_ + lane * 4];
            dot[i] = mv.x * k4.x + mv.y * k4.y + mv.z * k4.z + mv.w * k4.w;
            ssq[i] = mv.x * mv.x + mv.y * mv.y + mv.z * mv.z + mv.w * mv.w;
        }
#pragma unroll
        for (int off = 16; off > 0; off >>= 1) {
#pragma unroll
            for (int i = 0; i < 4; i++) {
                dot[i] += __shfl_xor_sync(0xffffffffu, dot[i], off);
                ssq[i] += __shfl_xor_sync(0xffffffffu, ssq[i], off);
            }
        }
        if (lane < 4) {
            const int i = lane;
            float sim = dot[i] / (sqrtf(ssq[i]) * knorm + EPS);
            slog[nbase + i] = beta * sim;
        }
    }
    __syncthreads();

    // ---- softmax -> gate -> shift conv -> sharpen (1 elem per thread) ----
    float x = slog[tid];
    float lmax = x;
#pragma unroll
    for (int off = 16; off > 0; off >>= 1)
        lmax = fmaxf(lmax, __shfl_xor_sync(0xffffffffu, lmax, off));
    if (lane == 0) sred[warp] = lmax;
    __syncthreads();
    float bmax = sred[0];
#pragma unroll
    for (int k = 1; k < 32; k++) bmax = fmaxf(bmax, sred[k]);

    float p = expf(x - bmax);
    float lsum = p;
#pragma unroll
    for (int off = 16; off > 0; off >>= 1)
        lsum += __shfl_xor_sync(0xffffffffu, lsum, off);
    __syncthreads();
    if (lane == 0) sred[warp] = lsum;
    __syncthreads();
    float bsum = 0.f;
#pragma unroll
    for (int k = 0; k < 32; k++) bsum += sred[k];
    const float inv = 1.f / bsum;

    slog[tid] = g * (p * inv) + (1.f - g) * w_prev[(size_t)b * N_ + tid];   // w_g
    __syncthreads();

    float wt = s0 * slog[(tid + N_ - 1) & (N_ - 1)] + s1 * slog[tid]
             + s2 * slog[(tid + 1) & (N_ - 1)];
    float wpow = powf(wt + EPS, gamma);
    float lsum2 = wpow;
#pragma unroll
    for (int off = 16; off > 0; off >>= 1)
        lsum2 += __shfl_xor_sync(0xffffffffu, lsum2, off);
    __syncthreads();
    if (lane == 0) sred[warp] = lsum2;
    __syncthreads();
    float bsum2 = 0.f;
#pragma unroll
    for (int k = 0; k < 32; k++) bsum2 += sred[k];
    const float inv2 = 1.f / (bsum2 + EPS);

    const float wv = wpow * inv2;
    warr[tid] = wv;
    w_out[(size_t)b * N_ + tid] = wv;
    __syncthreads();

    // ---- pass 2: new_mem = mem*(1 - w e) + w a  (mem rows are L2 hits) ----
    float* outb = out_mem + (size_t)b * N_ * M_;
#pragma unroll
    for (int i0 = 0; i0 < 32; i0 += 4) {
        const int nbase = warp * 32 + i0;
#pragma unroll
        for (int i = 0; i < 4; i++) {
            const int n = nbase + i;
            const float w_ = warr[n];
            const size_t off = (size_t)n * M_ + lane * 4;
            float4 mv = __ldcs((const float4*)&memb[off]);   // last use: evict-first
            float4 r;
            r.x = mv.x * (1.f - w_ * ev.x) + w_ * av.x;
            r.y = mv.y * (1.f - w_ * ev.y) + w_ * av.y;
            r.z = mv.z * (1.f - w_ * ev.z) + w_ * av.z;
            r.w = mv.w * (1.f - w_ * ev.w) + w_ * av.w;
            __stcs((float4*)&outb[off], r);                  // evict-first write
        }
    }
}

// ---------------- launch ----------------
extern "C" void kernel_launch(void* const* d_in, const int* in_sizes, int n_in,
                              void* d_out, int out_size)
{
    const float* emb    = (const float*)d_in[0];
    const float* w_prev = (const float*)d_in[1];
    const float* mem    = (const float*)d_in[2];
    const float* fc_w   = (const float*)d_in[3];
    const float* fc_b   = (const float*)d_in[4];

    float* out_w   = (float*)d_out;
    float* out_mem = out_w + (size_t)B_ * N_;

    dim3 g1((OUTF + 63) / 64, B_ / 64, KSPLIT);
    k1_gemm<<<g1, 256>>>(emb, fc_w);
    k1b_reduce<<<(B_ * OUTF + 255) / 256, 256>>>(fc_b);
    k2_act<<<B_, 128>>>();

    // pad SMEM to >114 KB to force 1 CTA/SM (protect L2 residency)
    const int smemF = 120 * 1024;
    cudaFuncSetAttribute(kF_fused, cudaFuncAttributeMaxDynamicSharedMemorySize, smemF);
    kF_fused<<<B_, 1024, smemF>>>(mem, w_prev, out_w, out_mem);
}